// round 4
// baseline (speedup 1.0000x reference)
#include <cuda_runtime.h>

// Problem constants
#define B_    32
#define L_    16
#define O_    256
#define DM_   64
#define CELLS 8192      // B*O
#define NROWS 131072    // B*L*O

typedef unsigned long long ull;

// ---------------- packed f32x2 helpers (Blackwell FFMA2 path) ---------------
__device__ __forceinline__ ull pack2(float lo, float hi) {
    ull d; asm("mov.b64 %0, {%1, %2};" : "=l"(d) : "f"(lo), "f"(hi)); return d;
}
__device__ __forceinline__ void unpack2(ull v, float& lo, float& hi) {
    asm("mov.b64 {%0, %1}, %2;" : "=f"(lo), "=f"(hi) : "l"(v));
}
__device__ __forceinline__ ull fma2(ull a, ull b, ull c) {
    ull d; asm("fma.rn.f32x2 %0, %1, %2, %3;" : "=l"(d) : "l"(a), "l"(b), "l"(c)); return d;
}

// ---------------- scratch (__device__ globals: no allocations allowed) ------
__device__ float g_F[(size_t)CELLS * L_ * DM_];   // F = X@E, [cell][l][64]
__device__ float g_Wpre[128 * 256];               // [k][n] combined Wi_flow/Wh, gate-interleaved
__device__ float g_GbiasP[O_ * 256];              // per-o gate bias, permuted layout
__device__ float g_part[128 * 128];               // per-CTA LN partials
__device__ float g_mean[DM_];
__device__ float g_rstd[DM_];
__device__ float g_hlast[(size_t)CELLS * DM_];
__device__ float g_v[(size_t)CELLS * DM_];
__device__ float g_lv[(size_t)CELLS * DM_];

// ---------------- activation helpers ---------------------------------------
__device__ __forceinline__ float sigm_(float x) {
    return 1.0f / (1.0f + __expf(-x));
}
__device__ __forceinline__ float tanh_(float x) {
    float ax = fabsf(x);
    float e  = __expf(-2.0f * ax);
    float t  = (1.0f - e) / (1.0f + e);
    return (x < 0.0f) ? -t : t;
}

// ---------------- prep: softmax(-dis)@E -> Gbias ; weight repack ------------
__global__ void prep_kernel(const float* __restrict__ dis, const float* __restrict__ E,
                            const float* __restrict__ Wi,  const float* __restrict__ Wh,
                            const float* __restrict__ bi,  const float* __restrict__ bh)
{
    int bid = blockIdx.x, tid = threadIdx.x;
    if (bid < 256) {
        __shared__ float sh[256];
        __shared__ float red[256];
        __shared__ float fg[64];
        int o = bid;
        float x = -dis[o * 256 + tid];
        red[tid] = x; __syncthreads();
        for (int s = 128; s > 0; s >>= 1) { if (tid < s) red[tid] = fmaxf(red[tid], red[tid + s]); __syncthreads(); }
        float m = red[0];
        __syncthreads();
        float e = __expf(x - m);
        sh[tid] = e;
        red[tid] = e; __syncthreads();
        for (int s = 128; s > 0; s >>= 1) { if (tid < s) red[tid] += red[tid + s]; __syncthreads(); }
        float inv = 1.0f / red[0];
        __syncthreads();
        {
            int ei = tid & 63, ch = tid >> 6;
            float a = 0.0f;
            int k0 = ch * 64;
            for (int k = k0; k < k0 + 64; k++) a = fmaf(sh[k], E[k * 64 + ei], a);
            red[tid] = a;
            __syncthreads();
            if (tid < 64) fg[tid] = (red[tid] + red[64 + tid] + red[128 + tid] + red[192 + tid]) * inv;
            __syncthreads();
        }
        int n = tid;
        int g = (n & 3) * 64 + (n >> 2);
        float acc = bi[g] + bh[g];
        const float* wrow = Wi + g * 128 + 64;
        #pragma unroll 8
        for (int ei = 0; ei < 64; ei++) acc = fmaf(fg[ei], wrow[ei], acc);
        g_GbiasP[o * 256 + n] = acc;
    } else {
        int k = bid - 256;
        int n = tid;
        int g = (n & 3) * 64 + (n >> 2);
        g_Wpre[k * 256 + n] = (k < 64) ? Wi[g * 128 + k] : Wh[g * 64 + (k - 64)];
    }
}

// ---------------- GEMM1: F = X @ E  (131072x256 @ 256x64) -------------------
// Xs stored as DUPLICATED f32x2 pairs -> pure FFMA2 inner loop (no MOV).
// Layout: Xs_d (ull[32][130]) at smem offset 0, Es (float[256][64]) after.
#define XS_STR 130
#define G1_SMEM (32 * XS_STR * 8 + 256 * 64 * 4)
__global__ void __launch_bounds__(256, 2) gemm1_full(const float* __restrict__ X,
                                                     const float* __restrict__ E)
{
    extern __shared__ float sm[];
    ull*   Xs = (ull*)sm;                       // [32][130] duplicated pairs
    float* Es = sm + (32 * XS_STR * 2);         // [256][64]
    const int tid = threadIdx.x;
    const int tx = tid & 15, ty = tid >> 4;     // tx: 16 n-groups of 4; ty: 16 m-groups of 8
    const int row0 = blockIdx.x * 128;

    for (int i = tid; i < 256 * 64; i += 256) Es[i] = E[i];

    ull acc2[8][2];
    #pragma unroll
    for (int c = 0; c < 8; c++) { acc2[c][0] = 0ull; acc2[c][1] = 0ull; }

    for (int chunk = 0; chunk < 8; chunk++) {
        int k0 = chunk * 32;
        __syncthreads();
        for (int i = tid; i < 4096; i += 256) {
            int rr = i >> 5, kk = i & 31;
            float v = X[(size_t)(row0 + rr) * 256 + k0 + kk];
            ((float2*)&Xs[kk * XS_STR + rr])[0] = make_float2(v, v);
        }
        __syncthreads();
        #pragma unroll
        for (int kk = 0; kk < 32; kk++) {
            ulonglong2 p0 = *(const ulonglong2*)&Xs[kk * XS_STR + ty * 8];
            ulonglong2 p1 = *(const ulonglong2*)&Xs[kk * XS_STR + ty * 8 + 2];
            ulonglong2 p2 = *(const ulonglong2*)&Xs[kk * XS_STR + ty * 8 + 4];
            ulonglong2 p3 = *(const ulonglong2*)&Xs[kk * XS_STR + ty * 8 + 6];
            ulonglong2 bq = *(const ulonglong2*)&Es[(k0 + kk) * 64 + tx * 4];
            ull ad[8] = {p0.x, p0.y, p1.x, p1.y, p2.x, p2.y, p3.x, p3.y};
            #pragma unroll
            for (int c = 0; c < 8; c++) {
                acc2[c][0] = fma2(ad[c], bq.x, acc2[c][0]);
                acc2[c][1] = fma2(ad[c], bq.y, acc2[c][1]);
            }
        }
    }
    #pragma unroll
    for (int c = 0; c < 8; c++) {
        int row = row0 + ty * 8 + c;               // (b*L + l)*O + o
        int b = row >> 12;
        int l = (row >> 8) & 15;
        int o = row & 255;
        size_t fi = ((size_t)((b << 8) | o) * 16 + l) * 64 + tx * 4;
        float v0, v1, v2, v3;
        unpack2(acc2[c][0], v0, v1);
        unpack2(acc2[c][1], v2, v3);
        *(float4*)&g_F[fi] = make_float4(v0, v1, v2, v3);
    }
}

// ---------------- fused input-GEMM + LSTM (persistent per 64 cells) ---------
// SMEM: Ws float[128][256] (128KB) + As_d ull[128][66] (duplicated activations).
// As_d rows 0..63 = F(l) (row e, dup pairs per cell), rows 64..127 = h (row dm).
// Inner loop: 6 LDS.128 + 32 FFMA2 per k -> no MOV, no packing.
#define AS_STR 66
#define LSTM_SMEM (32768 * 4 + 128 * AS_STR * 8)
__global__ void __launch_bounds__(256, 1) lstm_kernel()
{
    extern __shared__ float sm[];
    float* Ws = sm;                       // 32768 floats
    ull*   As = (ull*)(sm + 32768);       // [128][66] duplicated pairs
    const int tid = threadIdx.x;
    const int tx = tid & 31, ty = tid >> 5;   // tx: n-quads (dm=tx & dm=tx+32); ty: 8 cell-groups
    const int cellbase = blockIdx.x * 64;
    const int obase = cellbase & 255;

    for (int i = tid; i < 32768; i += 256) Ws[i] = g_Wpre[i];
    for (int i = tid; i < 64 * AS_STR; i += 256) As[64 * AS_STR + i] = 0ull;   // h = 0
    for (int i = tid; i < 4096; i += 256) {                                    // stage F(0)
        int cc = i >> 6, e = i & 63;
        float v = g_F[((size_t)(cellbase + cc) * 16 + 0) * 64 + e];
        ((float2*)&As[e * AS_STR + cc])[0] = make_float2(v, v);
    }

    // gate bias: register-resident for all 16 steps
    ull bias2[8][4];
    #pragma unroll
    for (int c = 0; c < 8; c++) {
        const float* gb = &g_GbiasP[(obase + ty * 8 + c) * 256];
        float4 b0 = *(const float4*)&gb[tx * 4];
        float4 b1 = *(const float4*)&gb[128 + tx * 4];
        bias2[c][0] = pack2(b0.x, b0.y);
        bias2[c][1] = pack2(b0.z, b0.w);
        bias2[c][2] = pack2(b1.x, b1.y);
        bias2[c][3] = pack2(b1.z, b1.w);
    }
    __syncthreads();

    float cs[16];
    #pragma unroll
    for (int i = 0; i < 16; i++) cs[i] = 0.0f;
    float ssum0 = 0.0f, ssum1 = 0.0f, ssq0 = 0.0f, ssq1 = 0.0f;

    for (int l = 0; l < 16; l++) {
        // prefetch F(l+1) into registers (hidden behind the GEMM)
        float fbuf[16];
        if (l < 15) {
            #pragma unroll
            for (int j = 0; j < 16; j++) {
                int i = tid + j * 256;
                int cc = i >> 6, e = i & 63;
                fbuf[j] = g_F[((size_t)(cellbase + cc) * 16 + (l + 1)) * 64 + e];
            }
        }

        ull acc2[8][4];
        #pragma unroll
        for (int c = 0; c < 8; c++)
            #pragma unroll
            for (int j = 0; j < 4; j++) acc2[c][j] = bias2[c][j];

        // 64x256x128 GEMM: z = [F(l)|h] @ [Wi_flow|Wh]^T (gate-permuted, FFMA2)
        #pragma unroll 4
        for (int k = 0; k < 128; k++) {
            ulonglong2 p0 = *(const ulonglong2*)&As[k * AS_STR + ty * 8];
            ulonglong2 p1 = *(const ulonglong2*)&As[k * AS_STR + ty * 8 + 2];
            ulonglong2 p2 = *(const ulonglong2*)&As[k * AS_STR + ty * 8 + 4];
            ulonglong2 p3 = *(const ulonglong2*)&As[k * AS_STR + ty * 8 + 6];
            ulonglong2 w0 = *(const ulonglong2*)&Ws[k * 256 + tx * 4];
            ulonglong2 w1 = *(const ulonglong2*)&Ws[k * 256 + 128 + tx * 4];
            ull ad[8] = {p0.x, p0.y, p1.x, p1.y, p2.x, p2.y, p3.x, p3.y};
            #pragma unroll
            for (int c = 0; c < 8; c++) {
                acc2[c][0] = fma2(ad[c], w0.x, acc2[c][0]);
                acc2[c][1] = fma2(ad[c], w0.y, acc2[c][1]);
                acc2[c][2] = fma2(ad[c], w1.x, acc2[c][2]);
                acc2[c][3] = fma2(ad[c], w1.y, acc2[c][3]);
            }
        }
        __syncthreads();   // all GEMM reads of As done

        // gates + h writeback (duplicated) + F(l+1) commit (duplicated)
        #pragma unroll
        for (int c = 0; c < 8; c++) {
            #pragma unroll
            for (int hf = 0; hf < 2; hf++) {
                float zi, zf, zg, zo;
                unpack2(acc2[c][hf * 2 + 0], zi, zf);
                unpack2(acc2[c][hf * 2 + 1], zg, zo);
                float ig  = sigm_(zi);
                float fgt = sigm_(zf);
                float gg  = tanh_(zg);
                float og  = sigm_(zo);
                float cn = fmaf(fgt, cs[hf * 8 + c], ig * gg);
                cs[hf * 8 + c] = cn;
                float h = og * tanh_(cn);
                int dm = tx + hf * 32;
                ((float2*)&As[(64 + dm) * AS_STR + ty * 8 + c])[0] = make_float2(h, h);
                if (hf == 0) { ssum0 += h; ssq0 = fmaf(h, h, ssq0); }
                else         { ssum1 += h; ssq1 = fmaf(h, h, ssq1); }
                if (l == 15)
                    g_hlast[(size_t)(cellbase + ty * 8 + c) * 64 + dm] = h;
            }
        }
        if (l < 15) {
            #pragma unroll
            for (int j = 0; j < 16; j++) {
                int i = tid + j * 256;
                int cc = i >> 6, e = i & 63;
                ((float2*)&As[e * AS_STR + cc])[0] = make_float2(fbuf[j], fbuf[j]);
            }
        }
        __syncthreads();
    }

    // deterministic LN partials (reuse As scratch as floats)
    float* red = (float*)As;
    red[tx * 8 + ty]               = ssum0;
    red[(tx + 32) * 8 + ty]        = ssum1;
    red[512 + tx * 8 + ty]         = ssq0;
    red[512 + (tx + 32) * 8 + ty]  = ssq1;
    __syncthreads();
    if (tid < 128) {
        int base = (tid < 64) ? (tid * 8) : (512 + (tid - 64) * 8);
        float s = 0.0f;
        #pragma unroll
        for (int j = 0; j < 8; j++) s += red[base + j];
        g_part[blockIdx.x * 128 + tid] = s;
    }
}

// ---------------- LN stats finalize (parallel: one block per feature) -------
__global__ void stats_kernel()
{
    __shared__ float rs[128], rq[128];
    int d = blockIdx.x, c = threadIdx.x;   // 64 blocks x 128 threads
    rs[c] = g_part[c * 128 + d];
    rq[c] = g_part[c * 128 + 64 + d];
    __syncthreads();
    for (int st = 64; st > 0; st >>= 1) {
        if (c < st) { rs[c] += rs[c + st]; rq[c] += rq[c + st]; }
        __syncthreads();
    }
    if (c == 0) {
        const float N = 131072.0f;
        float mean = rs[0] / N;
        float var  = rq[0] / N - mean * mean;
        g_mean[d] = mean;
        g_rstd[d] = rsqrtf(var + 1e-5f);
    }
}

// ---------------- v = LN(h_last), lv = v @ Wl^T + bl ------------------------
__global__ void vlv_kernel(const float* __restrict__ gamma, const float* __restrict__ beta,
                           const float* __restrict__ Wl,    const float* __restrict__ bl)
{
    __shared__ float WlT[64 * 65];
    __shared__ float vs[4 * 64];
    int tid = threadIdx.x;
    for (int i = tid; i < 4096; i += 256) {
        int j = i >> 6, e = i & 63;
        WlT[e * 65 + j] = Wl[i];
    }
    int cl = tid >> 6, e0 = tid & 63;
    int cell = blockIdx.x * 4 + cl;
    float h = g_hlast[(size_t)cell * 64 + e0];
    float v = fmaf((h - g_mean[e0]) * g_rstd[e0], gamma[e0], beta[e0]);
    g_v[(size_t)cell * 64 + e0] = v;
    vs[cl * 64 + e0] = v;
    __syncthreads();
    int j = e0;
    float acc = bl[j];
    #pragma unroll
    for (int e = 0; e < 64; e++) acc = fmaf(vs[cl * 64 + e], WlT[e * 65 + j], acc);
    g_lv[(size_t)cell * 64 + j] = acc;
}

// ---------------- out[b,o,d] = sum_e lv[b,o,e]*v[b,d,e] ---------------------
__global__ void out_kernel(float* __restrict__ out)
{
    __shared__ float As2[64 * 68];
    __shared__ float Bs2[64 * 68];
    int bid = blockIdx.x;
    int b = bid >> 4, ot = (bid >> 2) & 3, dt = bid & 3;
    int tid = threadIdx.x;
    for (int i = tid; i < 4096; i += 256) {
        int r = i >> 6, e = i & 63;
        As2[e * 68 + r] = g_lv[((size_t)(b * 256 + ot * 64 + r)) * 64 + e];
        Bs2[e * 68 + r] = g_v [((size_t)(b * 256 + dt * 64 + r)) * 64 + e];
    }
    __syncthreads();
    int tx = tid & 15, ty = tid >> 4;
    int o0 = ty * 4, d0 = tx * 4;
    float acc[4][4];
    #pragma unroll
    for (int i = 0; i < 4; i++)
        #pragma unroll
        for (int j = 0; j < 4; j++) acc[i][j] = 0.0f;
    #pragma unroll 8
    for (int e = 0; e < 64; e++) {
        float4 a = *(const float4*)&As2[e * 68 + o0];
        float4 q = *(const float4*)&Bs2[e * 68 + d0];
        float av[4] = {a.x, a.y, a.z, a.w};
        float qv[4] = {q.x, q.y, q.z, q.w};
        #pragma unroll
        for (int i = 0; i < 4; i++)
            #pragma unroll
            for (int j = 0; j < 4; j++)
                acc[i][j] = fmaf(av[i], qv[j], acc[i][j]);
    }
    #pragma unroll
    for (int i = 0; i < 4; i++) {
        size_t oi = ((size_t)(b * 256 + ot * 64 + o0 + i)) * 256 + dt * 64 + d0;
        *(float4*)&out[oi] = make_float4(acc[i][0], acc[i][1], acc[i][2], acc[i][3]);
    }
}

// ---------------- launch -----------------------------------------------------
extern "C" void kernel_launch(void* const* d_in, const int* in_sizes, int n_in,
                              void* d_out, int out_size)
{
    const float* X     = (const float*)d_in[0];
    const float* dis   = (const float*)d_in[1];
    const float* E     = (const float*)d_in[2];
    const float* Wi    = (const float*)d_in[3];
    const float* Wh    = (const float*)d_in[4];
    const float* bi    = (const float*)d_in[5];
    const float* bh    = (const float*)d_in[6];
    const float* gamma = (const float*)d_in[7];
    const float* beta  = (const float*)d_in[8];
    const float* Wl    = (const float*)d_in[9];
    const float* bl    = (const float*)d_in[10];
    float* out = (float*)d_out;

    cudaFuncSetAttribute(gemm1_full, cudaFuncAttributeMaxDynamicSharedMemorySize, G1_SMEM);
    cudaFuncSetAttribute(lstm_kernel, cudaFuncAttributeMaxDynamicSharedMemorySize, LSTM_SMEM);

    prep_kernel<<<384, 256>>>(dis, E, Wi, Wh, bi, bh);
    gemm1_full<<<1024, 256, G1_SMEM>>>(X, E);
    lstm_kernel<<<128, 256, LSTM_SMEM>>>();
    stats_kernel<<<64, 128>>>();
    vlv_kernel<<<2048, 256>>>(gamma, beta, Wl, bl);
    out_kernel<<<512, 256>>>(out);
}

// round 11
// speedup vs baseline: 1.3115x; 1.3115x over previous
#include <cuda_runtime.h>
#include <cuda_bf16.h>

// Problem constants
#define B_    32
#define L_    16
#define O_    256
#define DM_   64
#define CELLS 8192      // B*O
#define NROWS 131072    // B*L*O

// ---------------- scratch (__device__ globals) -------------------------------
__device__ float g_F[(size_t)CELLS * L_ * DM_];       // F = X@E, [cell][l][64] fp32
__device__ __nv_bfloat16 g_Fhl[(size_t)CELLS * L_ * 128]; // [cell][l][hi64|lo64]
__device__ __nv_bfloat16 g_Whi[128 * 256];            // [k][n] gate-permuted, bf16-hi
__device__ __nv_bfloat16 g_Wlo[128 * 256];            // bf16-lo residual
__device__ float g_GbiasP[O_ * 256];                  // per-o gate bias, permuted
__device__ float g_part[128 * 128];                   // per-CTA LN partials
__device__ float g_mean[DM_];
__device__ float g_rstd[DM_];
__device__ float g_hlast[(size_t)CELLS * DM_];
__device__ float g_v[(size_t)CELLS * DM_];
__device__ float g_lv[(size_t)CELLS * DM_];

// ---------------- helpers ----------------------------------------------------
__device__ __forceinline__ float sigm_(float x) { return 1.0f / (1.0f + __expf(-x)); }
__device__ __forceinline__ float tanh_(float x) {
    float ax = fabsf(x);
    float e  = __expf(-2.0f * ax);
    float t  = (1.0f - e) / (1.0f + e);
    return (x < 0.0f) ? -t : t;
}
__device__ __forceinline__ unsigned smem_u32(const void* p) {
    unsigned a;
    asm("{ .reg .u64 t; cvta.to.shared.u64 t, %1; cvt.u32.u64 %0, t; }" : "=r"(a) : "l"(p));
    return a;
}
__device__ __forceinline__ void ldm_x4(unsigned* r, unsigned saddr) {
    asm volatile("ldmatrix.sync.aligned.m8n8.x4.shared.b16 {%0,%1,%2,%3}, [%4];"
        : "=r"(r[0]), "=r"(r[1]), "=r"(r[2]), "=r"(r[3]) : "r"(saddr));
}
__device__ __forceinline__ void ldm_x2t(unsigned* r, unsigned saddr) {
    asm volatile("ldmatrix.sync.aligned.m8n8.x2.trans.shared.b16 {%0,%1}, [%2];"
        : "=r"(r[0]), "=r"(r[1]) : "r"(saddr));
}
__device__ __forceinline__ void mma16816(float* c, const unsigned* a, const unsigned* b) {
    asm volatile("mma.sync.aligned.m16n8k16.row.col.f32.bf16.bf16.f32 "
        "{%0,%1,%2,%3}, {%4,%5,%6,%7}, {%8,%9}, {%0,%1,%2,%3};"
        : "+f"(c[0]), "+f"(c[1]), "+f"(c[2]), "+f"(c[3])
        : "r"(a[0]), "r"(a[1]), "r"(a[2]), "r"(a[3]), "r"(b[0]), "r"(b[1]));
}

// Gate permutation: column n <-> (dm d, gate g):
//   n = 16*(d>>2) + 8*(g>>1) + 2*(d&3) + (g&1)
// inverse: T=n>>3; d = ((n&7)>>1) + 4*(T>>1); g = 2*(T&1) + (n&1); gate-row = g*64+d
__device__ __forceinline__ int grow_of_n(int n) {
    int T = n >> 3;
    int d = ((n & 7) >> 1) + 4 * (T >> 1);
    int g = 2 * (T & 1) + (n & 1);
    return g * 64 + d;
}

// ---------------- prep: softmax(-dis)@E -> Gbias ; weight split/repack -------
__global__ void prep_kernel(const float* __restrict__ dis, const float* __restrict__ E,
                            const float* __restrict__ Wi,  const float* __restrict__ Wh,
                            const float* __restrict__ bi,  const float* __restrict__ bh)
{
    int bid = blockIdx.x, tid = threadIdx.x;
    if (bid < 256) {
        __shared__ float sh[256];
        __shared__ float red[256];
        __shared__ float fg[64];
        int o = bid;
        float x = -dis[o * 256 + tid];
        red[tid] = x; __syncthreads();
        for (int s = 128; s > 0; s >>= 1) { if (tid < s) red[tid] = fmaxf(red[tid], red[tid + s]); __syncthreads(); }
        float m = red[0];
        __syncthreads();
        float e = __expf(x - m);
        sh[tid] = e;
        red[tid] = e; __syncthreads();
        for (int s = 128; s > 0; s >>= 1) { if (tid < s) red[tid] += red[tid + s]; __syncthreads(); }
        float inv = 1.0f / red[0];
        __syncthreads();
        {
            int ei = tid & 63, ch = tid >> 6;
            float a = 0.0f;
            int k0 = ch * 64;
            for (int k = k0; k < k0 + 64; k++) a = fmaf(sh[k], E[k * 64 + ei], a);
            red[tid] = a;
            __syncthreads();
            if (tid < 64) fg[tid] = (red[tid] + red[64 + tid] + red[128 + tid] + red[192 + tid]) * inv;
            __syncthreads();
        }
        int n = tid;
        int g = grow_of_n(n);
        float acc = bi[g] + bh[g];
        const float* wrow = Wi + g * 128 + 64;
        #pragma unroll 8
        for (int ei = 0; ei < 64; ei++) acc = fmaf(fg[ei], wrow[ei], acc);
        g_GbiasP[o * 256 + n] = acc;
    } else {
        int k = bid - 256;            // 0..127
        int n = tid;
        int g = grow_of_n(n);
        float w = (k < 64) ? Wi[g * 128 + k] : Wh[g * 64 + (k - 64)];
        __nv_bfloat16 hi = __float2bfloat16(w);
        float lof = w - __bfloat162float(hi);
        g_Whi[k * 256 + n] = hi;
        g_Wlo[k * 256 + n] = __float2bfloat16(lof);
    }
}

// ---------------- GEMM1: F = X @ E (131072x256 @ 256x64), plain FFMA --------
#define G1_SMEM ((256 * 64 + 32 * 132) * 4)
__global__ void __launch_bounds__(256, 2) gemm1_full(const float* __restrict__ X,
                                                     const float* __restrict__ E)
{
    extern __shared__ float sm[];
    float* Es = sm;                 // [256][64]
    float* Xs = sm + 256 * 64;      // [32][132]
    const int tid = threadIdx.x;
    const int tx = tid & 15, ty = tid >> 4;
    const int row0 = blockIdx.x * 128;

    for (int i = tid; i < 256 * 64; i += 256) Es[i] = E[i];

    float acc[8][4];
    #pragma unroll
    for (int c = 0; c < 8; c++)
        #pragma unroll
        for (int j = 0; j < 4; j++) acc[c][j] = 0.0f;

    for (int chunk = 0; chunk < 8; chunk++) {
        int k0 = chunk * 32;
        __syncthreads();
        for (int i = tid; i < 4096; i += 256) {
            int rr = i >> 5, kk = i & 31;
            Xs[kk * 132 + rr] = X[(size_t)(row0 + rr) * 256 + k0 + kk];
        }
        __syncthreads();
        #pragma unroll
        for (int kk = 0; kk < 32; kk++) {
            float4 a0 = *(const float4*)&Xs[kk * 132 + ty * 8];
            float4 a1 = *(const float4*)&Xs[kk * 132 + ty * 8 + 4];
            float4 bq = *(const float4*)&Es[(k0 + kk) * 64 + tx * 4];
            float av[8] = {a0.x, a0.y, a0.z, a0.w, a1.x, a1.y, a1.z, a1.w};
            float bv[4] = {bq.x, bq.y, bq.z, bq.w};
            #pragma unroll
            for (int c = 0; c < 8; c++)
                #pragma unroll
                for (int j = 0; j < 4; j++)
                    acc[c][j] = fmaf(av[c], bv[j], acc[c][j]);
        }
    }
    #pragma unroll
    for (int c = 0; c < 8; c++) {
        int row = row0 + ty * 8 + c;               // (b*L + l)*O + o
        int b = row >> 12;
        int l = (row >> 8) & 15;
        int o = row & 255;
        size_t fi = ((size_t)((b << 8) | o) * 16 + l) * 64 + tx * 4;
        *(float4*)&g_F[fi] = make_float4(acc[c][0], acc[c][1], acc[c][2], acc[c][3]);
    }
}

// ---------------- fsplit: F fp32 -> bf16 hi/lo, [row][hi64|lo64] ------------
__global__ void fsplit_kernel()
{
    size_t i4 = (size_t)blockIdx.x * 256 + threadIdx.x;   // grid 8192 -> 2.097M float4
    size_t base = i4 * 4;
    float4 v = *(const float4*)&g_F[base];
    size_t row = base >> 6;
    int e0 = (int)(base & 63);
    __nv_bfloat16* dst = &g_Fhl[row * 128];
    __nv_bfloat16 h0 = __float2bfloat16(v.x), h1 = __float2bfloat16(v.y);
    __nv_bfloat16 h2 = __float2bfloat16(v.z), h3 = __float2bfloat16(v.w);
    __nv_bfloat16 l0 = __float2bfloat16(v.x - __bfloat162float(h0));
    __nv_bfloat16 l1 = __float2bfloat16(v.y - __bfloat162float(h1));
    __nv_bfloat16 l2 = __float2bfloat16(v.z - __bfloat162float(h2));
    __nv_bfloat16 l3 = __float2bfloat16(v.w - __bfloat162float(h3));
    *(__nv_bfloat162*)&dst[e0]          = __nv_bfloat162(h0, h1);
    *(__nv_bfloat162*)&dst[e0 + 2]      = __nv_bfloat162(h2, h3);
    *(__nv_bfloat162*)&dst[64 + e0]     = __nv_bfloat162(l0, l1);
    *(__nv_bfloat162*)&dst[64 + e0 + 2] = __nv_bfloat162(l2, l3);
}

// ---------------- LSTM: bf16x3 tensor-core recurrence ------------------------
// SMEM (bytes): Whi[128][264h]=67584 | Wlo=67584 | Ahi[64][136h]=17408 | Alo=17408
// A rows k=0..63: F(l) hi/lo ; k=64..127: h hi/lo.  Row strides odd*16B -> ldmatrix conflict-free.
#define LSTM_SMEM (67584 * 2 + 17408 * 2)
__global__ void __launch_bounds__(256, 1) lstm_kernel()
{
    extern __shared__ char smc[];
    __nv_bfloat16* Whi = (__nv_bfloat16*)smc;
    __nv_bfloat16* Wlo = (__nv_bfloat16*)(smc + 67584);
    char* AhiB = smc + 135168;
    char* AloB = smc + 152576;

    const int tid  = threadIdx.x;
    const int wid  = tid >> 5, lane = tid & 31;
    const int mw = wid & 1, nw = wid >> 1;       // warp grid: 2(m) x 4(n)
    const int q = lane & 3, r = lane >> 2;
    const int cellbase = blockIdx.x * 64;
    const int obase = cellbase & 255;

    // stage W (hi/lo) with 264-half padded rows
    for (int i = tid; i < 4096; i += 256) {
        int k = i >> 5, n0 = (i & 31) * 8;
        *(uint4*)((char*)Whi + k * 528 + n0 * 2) = *(const uint4*)((const char*)g_Whi + k * 512 + n0 * 2);
        *(uint4*)((char*)Wlo + k * 528 + n0 * 2) = *(const uint4*)((const char*)g_Wlo + k * 512 + n0 * 2);
    }
    // zero h rows (bytes 128..255 of each 272B A row)
    for (int i = tid; i < 512; i += 256) {
        int cell = i >> 3, off = 128 + (i & 7) * 16;
        *(uint4*)(AhiB + cell * 272 + off) = make_uint4(0, 0, 0, 0);
        *(uint4*)(AloB + cell * 272 + off) = make_uint4(0, 0, 0, 0);
    }
    // stage F(0)
    #pragma unroll
    for (int jj = 0; jj < 4; jj++) {
        int c = tid * 4 + jj;
        int cell = c >> 4, off = (c & 15) * 16;
        uint4 v = *(const uint4*)((const char*)g_Fhl + (((size_t)(cellbase + cell) * 16 + 0) * 256) + off);
        if (off < 128) *(uint4*)(AhiB + cell * 272 + off) = v;
        else           *(uint4*)(AloB + cell * 272 + (off - 128)) = v;
    }

    // bias preload (shape-matched to accum fragments)
    float bias[2][8][4];
    #pragma unroll
    for (int f = 0; f < 2; f++)
        #pragma unroll
        for (int nt = 0; nt < 8; nt++)
            #pragma unroll
            for (int ci = 0; ci < 4; ci++) {
                int o = obase + 32 * mw + 16 * f + r + 8 * (ci >> 1);
                int n = 64 * nw + 8 * nt + 2 * q + (ci & 1);
                bias[f][nt][ci] = g_GbiasP[o * 256 + n];
            }

    // ldmatrix per-thread address components
    const unsigned aHiB = smem_u32(AhiB), aLoB = smem_u32(AloB);
    const unsigned wHiB = smem_u32(Whi),  wLoB = smem_u32(Wlo);
    const int jj = lane >> 3, r8 = lane & 7;
    int am[2];
    #pragma unroll
    for (int mf = 0; mf < 2; mf++)
        am[mf] = (32 * mw + 16 * mf + (jj & 1) * 8 + r8) * 272 + ((jj >> 1) * 8) * 2;
    const int brow = lane & 15;
    const int nwoff = 64 * nw * 2;

    float cs[2][4][2];
    #pragma unroll
    for (int f = 0; f < 2; f++)
        #pragma unroll
        for (int j = 0; j < 4; j++) { cs[f][j][0] = 0.0f; cs[f][j][1] = 0.0f; }
    float ssum[4] = {0, 0, 0, 0}, ssq[4] = {0, 0, 0, 0};

    for (int l = 0; l < 16; l++) {
        __syncthreads();   // A (h + F(l)) visible

        // prefetch F(l+1), hidden behind MMA phase
        uint4 fbuf[4];
        if (l < 15) {
            #pragma unroll
            for (int jj2 = 0; jj2 < 4; jj2++) {
                int c = tid * 4 + jj2;
                int cell = c >> 4, off = (c & 15) * 16;
                fbuf[jj2] = *(const uint4*)((const char*)g_Fhl +
                              (((size_t)(cellbase + cell) * 16 + (l + 1)) * 256) + off);
            }
        }

        // accumulators init from bias
        float acc[2][8][4];
        #pragma unroll
        for (int f = 0; f < 2; f++)
            #pragma unroll
            for (int nt = 0; nt < 8; nt++)
                #pragma unroll
                for (int ci = 0; ci < 4; ci++) acc[f][nt][ci] = bias[f][nt][ci];

        // MMA phase: z = [F|h] @ W^T, bf16x3 (AhBh + AhBl + AlBh)
        #pragma unroll
        for (int kt = 0; kt < 8; kt++) {
            unsigned ah[2][4], al[2][4];
            #pragma unroll
            for (int mf = 0; mf < 2; mf++) {
                ldm_x4(ah[mf], aHiB + am[mf] + kt * 32);
                ldm_x4(al[mf], aLoB + am[mf] + kt * 32);
            }
            unsigned bbase = (kt * 16 + brow) * 528 + nwoff;
            #pragma unroll
            for (int nt = 0; nt < 8; nt++) {
                unsigned bh2[2], bl2[2];
                ldm_x2t(bh2, wHiB + bbase + nt * 16);
                ldm_x2t(bl2, wLoB + bbase + nt * 16);
                mma16816(acc[0][nt], ah[0], bh2);
                mma16816(acc[0][nt], ah[0], bl2);
                mma16816(acc[0][nt], al[0], bh2);
                mma16816(acc[1][nt], ah[1], bh2);
                mma16816(acc[1][nt], ah[1], bl2);
                mma16816(acc[1][nt], al[1], bh2);
            }
        }
        __syncthreads();   // all reads of A done

        // gate phase
        #pragma unroll
        for (int f = 0; f < 2; f++)
            #pragma unroll
            for (int j = 0; j < 4; j++)
                #pragma unroll
                for (int rr = 0; rr < 2; rr++) {
                    float zi = acc[f][2 * j][2 * rr + 0];
                    float zf = acc[f][2 * j][2 * rr + 1];
                    float zg = acc[f][2 * j + 1][2 * rr + 0];
                    float zo = acc[f][2 * j + 1][2 * rr + 1];
                    float ig  = sigm_(zi);
                    float fgt = sigm_(zf);
                    float gg  = tanh_(zg);
                    float og  = sigm_(zo);
                    float cn = fmaf(fgt, cs[f][j][rr], ig * gg);
                    cs[f][j][rr] = cn;
                    float h = og * tanh_(cn);
                    int cell = 32 * mw + 16 * f + 8 * rr + r;
                    int dm = q + 16 * nw + 4 * j;
                    __nv_bfloat16 hh = __float2bfloat16(h);
                    __nv_bfloat16 hl = __float2bfloat16(h - __bfloat162float(hh));
                    *(__nv_bfloat16*)(AhiB + cell * 272 + 128 + 2 * dm) = hh;
                    *(__nv_bfloat16*)(AloB + cell * 272 + 128 + 2 * dm) = hl;
                    ssum[j] += h;
                    ssq[j] = fmaf(h, h, ssq[j]);
                    if (l == 15)
                        g_hlast[(size_t)(cellbase + cell) * 64 + dm] = h;
                }
        // commit F(l+1)
        if (l < 15) {
            #pragma unroll
            for (int jj2 = 0; jj2 < 4; jj2++) {
                int c = tid * 4 + jj2;
                int cell = c >> 4, off = (c & 15) * 16;
                if (off < 128) *(uint4*)(AhiB + cell * 272 + off) = fbuf[jj2];
                else           *(uint4*)(AloB + cell * 272 + (off - 128)) = fbuf[jj2];
            }
        }
    }
    __syncthreads();

    // deterministic LN partials: red[dm][slot], slot = r + 8*mw (16 slots/dm)
    float* red = (float*)AhiB;
    int slot = r + 8 * mw;
    #pragma unroll
    for (int j = 0; j < 4; j++) {
        int dm = q + 16 * nw + 4 * j;
        red[dm * 16 + slot]        = ssum[j];
        red[1024 + dm * 16 + slot] = ssq[j];
    }
    __syncthreads();
    if (tid < 128) {
        int d = tid & 63;
        int base = (tid < 64) ? (d * 16) : (1024 + d * 16);
        float s = 0.0f;
        #pragma unroll
        for (int i = 0; i < 16; i++) s += red[base + i];
        g_part[blockIdx.x * 128 + ((tid < 64) ? d : (64 + d))] = s;
    }
}

// ---------------- LN stats finalize ------------------------------------------
__global__ void stats_kernel()
{
    __shared__ float rs[128], rq[128];
    int d = blockIdx.x, c = threadIdx.x;
    rs[c] = g_part[c * 128 + d];
    rq[c] = g_part[c * 128 + 64 + d];
    __syncthreads();
    for (int st = 64; st > 0; st >>= 1) {
        if (c < st) { rs[c] += rs[c + st]; rq[c] += rq[c + st]; }
        __syncthreads();
    }
    if (c == 0) {
        const float N = 131072.0f;
        float mean = rs[0] / N;
        float var  = rq[0] / N - mean * mean;
        g_mean[d] = mean;
        g_rstd[d] = rsqrtf(var + 1e-5f);
    }
}

// ---------------- v = LN(h_last), lv = v @ Wl^T + bl --------------------------
__global__ void vlv_kernel(const float* __restrict__ gamma, const float* __restrict__ beta,
                           const float* __restrict__ Wl,    const float* __restrict__ bl)
{
    __shared__ float WlT[64 * 65];
    __shared__ float vs[4 * 64];
    int tid = threadIdx.x;
    for (int i = tid; i < 4096; i += 256) {
        int j = i >> 6, e = i & 63;
        WlT[e * 65 + j] = Wl[i];
    }
    int cl = tid >> 6, e0 = tid & 63;
    int cell = blockIdx.x * 4 + cl;
    float h = g_hlast[(size_t)cell * 64 + e0];
    float v = fmaf((h - g_mean[e0]) * g_rstd[e0], gamma[e0], beta[e0]);
    g_v[(size_t)cell * 64 + e0] = v;
    vs[cl * 64 + e0] = v;
    __syncthreads();
    int j = e0;
    float acc = bl[j];
    #pragma unroll
    for (int e = 0; e < 64; e++) acc = fmaf(vs[cl * 64 + e], WlT[e * 65 + j], acc);
    g_lv[(size_t)cell * 64 + j] = acc;
}

// ---------------- out[b,o,d] = sum_e lv[b,o,e]*v[b,d,e] -----------------------
__global__ void out_kernel(float* __restrict__ out)
{
    __shared__ float As2[64 * 68];
    __shared__ float Bs2[64 * 68];
    int bid = blockIdx.x;
    int b = bid >> 4, ot = (bid >> 2) & 3, dt = bid & 3;
    int tid = threadIdx.x;
    for (int i = tid; i < 4096; i += 256) {
        int rr = i >> 6, e = i & 63;
        As2[e * 68 + rr] = g_lv[((size_t)(b * 256 + ot * 64 + rr)) * 64 + e];
        Bs2[e * 68 + rr] = g_v [((size_t)(b * 256 + dt * 64 + rr)) * 64 + e];
    }
    __syncthreads();
    int tx = tid & 15, ty = tid >> 4;
    int o0 = ty * 4, d0 = tx * 4;
    float acc[4][4];
    #pragma unroll
    for (int i = 0; i < 4; i++)
        #pragma unroll
        for (int j = 0; j < 4; j++) acc[i][j] = 0.0f;
    #pragma unroll 8
    for (int e = 0; e < 64; e++) {
        float4 a = *(const float4*)&As2[e * 68 + o0];
        float4 qv4 = *(const float4*)&Bs2[e * 68 + d0];
        float av[4] = {a.x, a.y, a.z, a.w};
        float qv[4] = {qv4.x, qv4.y, qv4.z, qv4.w};
        #pragma unroll
        for (int i = 0; i < 4; i++)
            #pragma unroll
            for (int j = 0; j < 4; j++)
                acc[i][j] = fmaf(av[i], qv[j], acc[i][j]);
    }
    #pragma unroll
    for (int i = 0; i < 4; i++) {
        size_t oi = ((size_t)(b * 256 + ot * 64 + o0 + i)) * 256 + dt * 64 + d0;
        *(float4*)&out[oi] = make_float4(acc[i][0], acc[i][1], acc[i][2], acc[i][3]);
    }
}

// ---------------- launch ------------------------------------------------------
extern "C" void kernel_launch(void* const* d_in, const int* in_sizes, int n_in,
                              void* d_out, int out_size)
{
    const float* X     = (const float*)d_in[0];
    const float* dis   = (const float*)d_in[1];
    const float* E     = (const float*)d_in[2];
    const float* Wi    = (const float*)d_in[3];
    const float* Wh    = (const float*)d_in[4];
    const float* bi    = (const float*)d_in[5];
    const float* bh    = (const float*)d_in[6];
    const float* gamma = (const float*)d_in[7];
    const float* beta  = (const float*)d_in[8];
    const float* Wl    = (const float*)d_in[9];
    const float* bl    = (const float*)d_in[10];
    float* out = (float*)d_out;

    cudaFuncSetAttribute(gemm1_full, cudaFuncAttributeMaxDynamicSharedMemorySize, G1_SMEM);
    cudaFuncSetAttribute(lstm_kernel, cudaFuncAttributeMaxDynamicSharedMemorySize, LSTM_SMEM);

    prep_kernel<<<384, 256>>>(dis, E, Wi, Wh, bi, bh);   // idx0
    gemm1_full<<<1024, 256, G1_SMEM>>>(X, E);            // idx1
    fsplit_kernel<<<8192, 256>>>();                      // idx2
    lstm_kernel<<<128, 256, LSTM_SMEM>>>();              // idx3  <- ncu capture slot
    stats_kernel<<<64, 128>>>();                         // idx4
    vlv_kernel<<<2048, 256>>>(gamma, beta, Wl, bl);      // idx5
    out_kernel<<<512, 256>>>(out);                       // idx6
}

// round 16
// speedup vs baseline: 1.7493x; 1.3338x over previous
#include <cuda_runtime.h>
#include <cuda_bf16.h>

// Problem constants
#define B_    32
#define L_    16
#define O_    256
#define DM_   64
#define CELLS 8192      // B*O
#define NROWS 131072    // B*L*O

// ---------------- scratch (__device__ globals) -------------------------------
__device__ __nv_bfloat16 g_Fhl[(size_t)CELLS * L_ * 128]; // [cell][l][hi64|lo64]
__device__ __nv_bfloat16 g_Whi[128 * 256];            // [k][n] gate-permuted, bf16-hi
__device__ __nv_bfloat16 g_Wlo[128 * 256];            // bf16-lo residual
__device__ float g_GbiasP[O_ * 256];                  // per-o gate bias, permuted
__device__ float g_part[128 * 128];                   // per-CTA LN partials
__device__ float g_mean[DM_];
__device__ float g_rstd[DM_];
__device__ float g_hlast[(size_t)CELLS * DM_];
__device__ float g_v[(size_t)CELLS * DM_];
__device__ float g_lv[(size_t)CELLS * DM_];

// ---------------- helpers ----------------------------------------------------
__device__ __forceinline__ float sigm_(float x) { return 1.0f / (1.0f + __expf(-x)); }
__device__ __forceinline__ float tanh_(float x) {
    float ax = fabsf(x);
    float e  = __expf(-2.0f * ax);
    float t  = (1.0f - e) / (1.0f + e);
    return (x < 0.0f) ? -t : t;
}
__device__ __forceinline__ unsigned smem_u32(const void* p) {
    unsigned a;
    asm("{ .reg .u64 t; cvta.to.shared.u64 t, %1; cvt.u32.u64 %0, t; }" : "=r"(a) : "l"(p));
    return a;
}
__device__ __forceinline__ void ldm_x4(unsigned* r, unsigned saddr) {
    asm volatile("ldmatrix.sync.aligned.m8n8.x4.shared.b16 {%0,%1,%2,%3}, [%4];"
        : "=r"(r[0]), "=r"(r[1]), "=r"(r[2]), "=r"(r[3]) : "r"(saddr));
}
__device__ __forceinline__ void ldm_x2t(unsigned* r, unsigned saddr) {
    asm volatile("ldmatrix.sync.aligned.m8n8.x2.trans.shared.b16 {%0,%1}, [%2];"
        : "=r"(r[0]), "=r"(r[1]) : "r"(saddr));
}
__device__ __forceinline__ void mma16816(float* c, const unsigned* a, const unsigned* b) {
    asm volatile("mma.sync.aligned.m16n8k16.row.col.f32.bf16.bf16.f32 "
        "{%0,%1,%2,%3}, {%4,%5,%6,%7}, {%8,%9}, {%0,%1,%2,%3};"
        : "+f"(c[0]), "+f"(c[1]), "+f"(c[2]), "+f"(c[3])
        : "r"(a[0]), "r"(a[1]), "r"(a[2]), "r"(a[3]), "r"(b[0]), "r"(b[1]));
}

// Gate permutation: column n <-> (dm d, gate g):
//   n = 16*(d>>2) + 8*(g>>1) + 2*(d&3) + (g&1)
__device__ __forceinline__ int grow_of_n(int n) {
    int T = n >> 3;
    int d = ((n & 7) >> 1) + 4 * (T >> 1);
    int g = 2 * (T & 1) + (n & 1);
    return g * 64 + d;
}

// ---------------- prep A: softmax(-dis)@E -> Gbias ---------------------------
__global__ void prep_bias_kernel(const float* __restrict__ dis, const float* __restrict__ E,
                                 const float* __restrict__ Wi,  const float* __restrict__ bi,
                                 const float* __restrict__ bh)
{
    __shared__ float sh[256];
    __shared__ float red[256];
    __shared__ float fg[64];
    int o = blockIdx.x, tid = threadIdx.x;
    float x = -dis[o * 256 + tid];
    red[tid] = x; __syncthreads();
    for (int s = 128; s > 0; s >>= 1) { if (tid < s) red[tid] = fmaxf(red[tid], red[tid + s]); __syncthreads(); }
    float m = red[0];
    __syncthreads();
    float e = __expf(x - m);
    sh[tid] = e;
    red[tid] = e; __syncthreads();
    for (int s = 128; s > 0; s >>= 1) { if (tid < s) red[tid] += red[tid + s]; __syncthreads(); }
    float inv = 1.0f / red[0];
    __syncthreads();
    {
        int ei = tid & 63, ch = tid >> 6;
        float a = 0.0f;
        int k0 = ch * 64;
        for (int k = k0; k < k0 + 64; k++) a = fmaf(sh[k], E[k * 64 + ei], a);
        red[tid] = a;
        __syncthreads();
        if (tid < 64) fg[tid] = (red[tid] + red[64 + tid] + red[128 + tid] + red[192 + tid]) * inv;
        __syncthreads();
    }
    int n = tid;
    int g = grow_of_n(n);
    float acc = bi[g] + bh[g];
    const float* wrow = Wi + g * 128 + 64;
    #pragma unroll 8
    for (int ei = 0; ei < 64; ei++) acc = fmaf(fg[ei], wrow[ei], acc);
    g_GbiasP[o * 256 + n] = acc;
}

// ---------------- prep B: weight split/repack ---------------------------------
__global__ void prep_w_kernel(const float* __restrict__ Wi, const float* __restrict__ Wh)
{
    int k = blockIdx.x;            // 0..127
    int n = threadIdx.x;
    int g = grow_of_n(n);
    float w = (k < 64) ? Wi[g * 128 + k] : Wh[g * 64 + (k - 64)];
    __nv_bfloat16 hi = __float2bfloat16(w);
    float lof = w - __bfloat162float(hi);
    g_Whi[k * 256 + n] = hi;
    g_Wlo[k * 256 + n] = __float2bfloat16(lof);
}

// ---------------- GEMM1 (tensor-core bf16x3): g_Fhl = split(X @ E) ------------
// Per CTA: BM=128 rows, N=64, K=256 (4 chunks of 64). Warp grid 4(m) x 2(n).
// SMEM: Ehi/Elo [256][72h] stride 144B ; Xhi/Xlo [128][72h] stride 144B (per chunk).
#define G2_SMEM (36864 * 2 + 18432 * 2)   // 110592 B
__global__ void __launch_bounds__(256, 2) gemm1_mma(const float* __restrict__ X,
                                                    const float* __restrict__ E,
                                                    int rowbase)
{
    extern __shared__ char smc[];
    __nv_bfloat16* Ehi = (__nv_bfloat16*)smc;             // stride 72 halves
    __nv_bfloat16* Elo = (__nv_bfloat16*)(smc + 36864);
    char* XhiB = smc + 73728;                              // stride 144 B
    char* XloB = smc + 92160;

    const int tid = threadIdx.x;
    const int wid = tid >> 5, lane = tid & 31;
    const int wm = wid & 3, wn = wid >> 2;
    const int q = lane & 3, r = lane >> 2;
    const int jj = lane >> 3, r8 = lane & 7;
    const int brow = lane & 15;
    const int row0 = rowbase + blockIdx.x * 128;

    // stage E hi/lo
    for (int i = tid; i < 16384; i += 256) {
        int k = i >> 6, e = i & 63;
        float w = E[i];
        __nv_bfloat16 hi = __float2bfloat16(w);
        Ehi[k * 72 + e] = hi;
        Elo[k * 72 + e] = __float2bfloat16(w - __bfloat162float(hi));
    }

    float acc[2][4][4];
    #pragma unroll
    for (int mf = 0; mf < 2; mf++)
        #pragma unroll
        for (int nt = 0; nt < 4; nt++)
            #pragma unroll
            for (int ci = 0; ci < 4; ci++) acc[mf][nt][ci] = 0.0f;

    const unsigned ehiB = smem_u32(Ehi), eloB = smem_u32(Elo);
    const unsigned xhiB = smem_u32(XhiB), xloB = smem_u32(XloB);
    int am[2];
    #pragma unroll
    for (int mf = 0; mf < 2; mf++)
        am[mf] = (wm * 32 + mf * 16 + (jj & 1) * 8 + r8) * 144 + (jj >> 1) * 16;

    for (int chunk = 0; chunk < 4; chunk++) {
        __syncthreads();
        // stage X chunk hi/lo: 128 rows x 64 k
        for (int i = tid; i < 2048; i += 256) {
            int row = i >> 4, kq = i & 15;
            float4 v = *(const float4*)&X[(size_t)(row0 + row) * 256 + chunk * 64 + kq * 4];
            __nv_bfloat16 h0 = __float2bfloat16(v.x), h1 = __float2bfloat16(v.y);
            __nv_bfloat16 h2 = __float2bfloat16(v.z), h3 = __float2bfloat16(v.w);
            __nv_bfloat16 l0 = __float2bfloat16(v.x - __bfloat162float(h0));
            __nv_bfloat16 l1 = __float2bfloat16(v.y - __bfloat162float(h1));
            __nv_bfloat16 l2 = __float2bfloat16(v.z - __bfloat162float(h2));
            __nv_bfloat16 l3 = __float2bfloat16(v.w - __bfloat162float(h3));
            char* ph = XhiB + row * 144 + kq * 8;
            char* pl = XloB + row * 144 + kq * 8;
            *(__nv_bfloat162*)(ph)     = __nv_bfloat162(h0, h1);
            *(__nv_bfloat162*)(ph + 4) = __nv_bfloat162(h2, h3);
            *(__nv_bfloat162*)(pl)     = __nv_bfloat162(l0, l1);
            *(__nv_bfloat162*)(pl + 4) = __nv_bfloat162(l2, l3);
        }
        __syncthreads();

        #pragma unroll
        for (int kt = 0; kt < 4; kt++) {
            unsigned ah[2][4], al[2][4];
            #pragma unroll
            for (int mf = 0; mf < 2; mf++) {
                ldm_x4(ah[mf], xhiB + am[mf] + kt * 32);
                ldm_x4(al[mf], xloB + am[mf] + kt * 32);
            }
            unsigned bb = (unsigned)(chunk * 64 + kt * 16 + brow) * 144 + wn * 64;
            #pragma unroll
            for (int nt = 0; nt < 4; nt++) {
                unsigned bh2[2], bl2[2];
                ldm_x2t(bh2, ehiB + bb + nt * 16);
                ldm_x2t(bl2, eloB + bb + nt * 16);
                mma16816(acc[0][nt], ah[0], bh2);
                mma16816(acc[0][nt], ah[0], bl2);
                mma16816(acc[0][nt], al[0], bh2);
                mma16816(acc[1][nt], ah[1], bh2);
                mma16816(acc[1][nt], ah[1], bl2);
                mma16816(acc[1][nt], al[1], bh2);
            }
        }
    }

    // epilogue: split accum -> g_Fhl [cell][l][hi64|lo64]
    #pragma unroll
    for (int mf = 0; mf < 2; mf++)
        #pragma unroll
        for (int ci = 0; ci < 2; ci++) {
            int rowg = row0 + wm * 32 + mf * 16 + r + ci * 8;   // (b*L + l)*O + o
            int b = rowg >> 12;
            int l = (rowg >> 8) & 15;
            int o = rowg & 255;
            size_t dst = ((size_t)((b << 8) | o) * 16 + l) * 128;
            #pragma unroll
            for (int nt = 0; nt < 4; nt++) {
                float v0 = acc[mf][nt][ci * 2 + 0];
                float v1 = acc[mf][nt][ci * 2 + 1];
                __nv_bfloat16 h0 = __float2bfloat16(v0), h1 = __float2bfloat16(v1);
                __nv_bfloat16 l0 = __float2bfloat16(v0 - __bfloat162float(h0));
                __nv_bfloat16 l1 = __float2bfloat16(v1 - __bfloat162float(h1));
                int e0 = wn * 32 + nt * 8 + 2 * q;
                *(__nv_bfloat162*)&g_Fhl[dst + e0]      = __nv_bfloat162(h0, h1);
                *(__nv_bfloat162*)&g_Fhl[dst + 64 + e0] = __nv_bfloat162(l0, l1);
            }
        }
}

// ---------------- LSTM: bf16x3 tensor-core recurrence (unchanged) ------------
#define LSTM_SMEM (67584 * 2 + 17408 * 2)
__global__ void __launch_bounds__(256, 1) lstm_kernel()
{
    extern __shared__ char smc[];
    __nv_bfloat16* Whi = (__nv_bfloat16*)smc;
    __nv_bfloat16* Wlo = (__nv_bfloat16*)(smc + 67584);
    char* AhiB = smc + 135168;
    char* AloB = smc + 152576;

    const int tid  = threadIdx.x;
    const int wid  = tid >> 5, lane = tid & 31;
    const int mw = wid & 1, nw = wid >> 1;       // warp grid: 2(m) x 4(n)
    const int q = lane & 3, r = lane >> 2;
    const int cellbase = blockIdx.x * 64;
    const int obase = cellbase & 255;

    for (int i = tid; i < 4096; i += 256) {
        int k = i >> 5, n0 = (i & 31) * 8;
        *(uint4*)((char*)Whi + k * 528 + n0 * 2) = *(const uint4*)((const char*)g_Whi + k * 512 + n0 * 2);
        *(uint4*)((char*)Wlo + k * 528 + n0 * 2) = *(const uint4*)((const char*)g_Wlo + k * 512 + n0 * 2);
    }
    for (int i = tid; i < 512; i += 256) {
        int cell = i >> 3, off = 128 + (i & 7) * 16;
        *(uint4*)(AhiB + cell * 272 + off) = make_uint4(0, 0, 0, 0);
        *(uint4*)(AloB + cell * 272 + off) = make_uint4(0, 0, 0, 0);
    }
    #pragma unroll
    for (int jj = 0; jj < 4; jj++) {
        int c = tid * 4 + jj;
        int cell = c >> 4, off = (c & 15) * 16;
        uint4 v = *(const uint4*)((const char*)g_Fhl + (((size_t)(cellbase + cell) * 16 + 0) * 256) + off);
        if (off < 128) *(uint4*)(AhiB + cell * 272 + off) = v;
        else           *(uint4*)(AloB + cell * 272 + (off - 128)) = v;
    }

    float bias[2][8][4];
    #pragma unroll
    for (int f = 0; f < 2; f++)
        #pragma unroll
        for (int nt = 0; nt < 8; nt++)
            #pragma unroll
            for (int ci = 0; ci < 4; ci++) {
                int o = obase + 32 * mw + 16 * f + r + 8 * (ci >> 1);
                int n = 64 * nw + 8 * nt + 2 * q + (ci & 1);
                bias[f][nt][ci] = g_GbiasP[o * 256 + n];
            }

    const unsigned aHiB = smem_u32(AhiB), aLoB = smem_u32(AloB);
    const unsigned wHiB = smem_u32(Whi),  wLoB = smem_u32(Wlo);
    const int jj = lane >> 3, r8 = lane & 7;
    int am[2];
    #pragma unroll
    for (int mf = 0; mf < 2; mf++)
        am[mf] = (32 * mw + 16 * mf + (jj & 1) * 8 + r8) * 272 + ((jj >> 1) * 8) * 2;
    const int brow = lane & 15;
    const int nwoff = 64 * nw * 2;

    float cs[2][4][2];
    #pragma unroll
    for (int f = 0; f < 2; f++)
        #pragma unroll
        for (int j = 0; j < 4; j++) { cs[f][j][0] = 0.0f; cs[f][j][1] = 0.0f; }
    float ssum[4] = {0, 0, 0, 0}, ssq[4] = {0, 0, 0, 0};

    for (int l = 0; l < 16; l++) {
        __syncthreads();

        uint4 fbuf[4];
        if (l < 15) {
            #pragma unroll
            for (int jj2 = 0; jj2 < 4; jj2++) {
                int c = tid * 4 + jj2;
                int cell = c >> 4, off = (c & 15) * 16;
                fbuf[jj2] = *(const uint4*)((const char*)g_Fhl +
                              (((size_t)(cellbase + cell) * 16 + (l + 1)) * 256) + off);
            }
        }

        float acc[2][8][4];
        #pragma unroll
        for (int f = 0; f < 2; f++)
            #pragma unroll
            for (int nt = 0; nt < 8; nt++)
                #pragma unroll
                for (int ci = 0; ci < 4; ci++) acc[f][nt][ci] = bias[f][nt][ci];

        #pragma unroll
        for (int kt = 0; kt < 8; kt++) {
            unsigned ah[2][4], al[2][4];
            #pragma unroll
            for (int mf = 0; mf < 2; mf++) {
                ldm_x4(ah[mf], aHiB + am[mf] + kt * 32);
                ldm_x4(al[mf], aLoB + am[mf] + kt * 32);
            }
            unsigned bbase = (kt * 16 + brow) * 528 + nwoff;
            #pragma unroll
            for (int nt = 0; nt < 8; nt++) {
                unsigned bh2[2], bl2[2];
                ldm_x2t(bh2, wHiB + bbase + nt * 16);
                ldm_x2t(bl2, wLoB + bbase + nt * 16);
                mma16816(acc[0][nt], ah[0], bh2);
                mma16816(acc[0][nt], ah[0], bl2);
                mma16816(acc[0][nt], al[0], bh2);
                mma16816(acc[1][nt], ah[1], bh2);
                mma16816(acc[1][nt], ah[1], bl2);
                mma16816(acc[1][nt], al[1], bh2);
            }
        }
        __syncthreads();

        #pragma unroll
        for (int f = 0; f < 2; f++)
            #pragma unroll
            for (int j = 0; j < 4; j++)
                #pragma unroll
                for (int rr = 0; rr < 2; rr++) {
                    float zi = acc[f][2 * j][2 * rr + 0];
                    float zf = acc[f][2 * j][2 * rr + 1];
                    float zg = acc[f][2 * j + 1][2 * rr + 0];
                    float zo = acc[f][2 * j + 1][2 * rr + 1];
                    float ig  = sigm_(zi);
                    float fgt = sigm_(zf);
                    float gg  = tanh_(zg);
                    float og  = sigm_(zo);
                    float cn = fmaf(fgt, cs[f][j][rr], ig * gg);
                    cs[f][j][rr] = cn;
                    float h = og * tanh_(cn);
                    int cell = 32 * mw + 16 * f + 8 * rr + r;
                    int dm = q + 16 * nw + 4 * j;
                    __nv_bfloat16 hh = __float2bfloat16(h);
                    __nv_bfloat16 hl = __float2bfloat16(h - __bfloat162float(hh));
                    *(__nv_bfloat16*)(AhiB + cell * 272 + 128 + 2 * dm) = hh;
                    *(__nv_bfloat16*)(AloB + cell * 272 + 128 + 2 * dm) = hl;
                    ssum[j] += h;
                    ssq[j] = fmaf(h, h, ssq[j]);
                    if (l == 15)
                        g_hlast[(size_t)(cellbase + cell) * 64 + dm] = h;
                }
        if (l < 15) {
            #pragma unroll
            for (int jj2 = 0; jj2 < 4; jj2++) {
                int c = tid * 4 + jj2;
                int cell = c >> 4, off = (c & 15) * 16;
                if (off < 128) *(uint4*)(AhiB + cell * 272 + off) = fbuf[jj2];
                else           *(uint4*)(AloB + cell * 272 + (off - 128)) = fbuf[jj2];
            }
        }
    }
    __syncthreads();

    float* red = (float*)AhiB;
    int slot = r + 8 * mw;
    #pragma unroll
    for (int j = 0; j < 4; j++) {
        int dm = q + 16 * nw + 4 * j;
        red[dm * 16 + slot]        = ssum[j];
        red[1024 + dm * 16 + slot] = ssq[j];
    }
    __syncthreads();
    if (tid < 128) {
        int d = tid & 63;
        int base = (tid < 64) ? (d * 16) : (1024 + d * 16);
        float s = 0.0f;
        #pragma unroll
        for (int i = 0; i < 16; i++) s += red[base + i];
        g_part[blockIdx.x * 128 + ((tid < 64) ? d : (64 + d))] = s;
    }
}

// ---------------- LN stats finalize ------------------------------------------
__global__ void stats_kernel()
{
    __shared__ float rs[128], rq[128];
    int d = blockIdx.x, c = threadIdx.x;
    rs[c] = g_part[c * 128 + d];
    rq[c] = g_part[c * 128 + 64 + d];
    __syncthreads();
    for (int st = 64; st > 0; st >>= 1) {
        if (c < st) { rs[c] += rs[c + st]; rq[c] += rq[c + st]; }
        __syncthreads();
    }
    if (c == 0) {
        const float N = 131072.0f;
        float mean = rs[0] / N;
        float var  = rq[0] / N - mean * mean;
        g_mean[d] = mean;
        g_rstd[d] = rsqrtf(var + 1e-5f);
    }
}

// ---------------- v = LN(h_last), lv = v @ Wl^T + bl --------------------------
__global__ void vlv_kernel(const float* __restrict__ gamma, const float* __restrict__ beta,
                           const float* __restrict__ Wl,    const float* __restrict__ bl)
{
    __shared__ float WlT[64 * 65];
    __shared__ float vs[4 * 64];
    int tid = threadIdx.x;
    for (int i = tid; i < 4096; i += 256) {
        int j = i >> 6, e = i & 63;
        WlT[e * 65 + j] = Wl[i];
    }
    int cl = tid >> 6, e0 = tid & 63;
    int cell = blockIdx.x * 4 + cl;
    float h = g_hlast[(size_t)cell * 64 + e0];
    float v = fmaf((h - g_mean[e0]) * g_rstd[e0], gamma[e0], beta[e0]);
    g_v[(size_t)cell * 64 + e0] = v;
    vs[cl * 64 + e0] = v;
    __syncthreads();
    int j = e0;
    float acc = bl[j];
    #pragma unroll
    for (int e = 0; e < 64; e++) acc = fmaf(vs[cl * 64 + e], WlT[e * 65 + j], acc);
    g_lv[(size_t)cell * 64 + j] = acc;
}

// ---------------- out[b,o,d] = sum_e lv[b,o,e]*v[b,d,e] -----------------------
__global__ void out_kernel(float* __restrict__ out)
{
    __shared__ float As2[64 * 68];
    __shared__ float Bs2[64 * 68];
    int bid = blockIdx.x;
    int b = bid >> 4, ot = (bid >> 2) & 3, dt = bid & 3;
    int tid = threadIdx.x;
    for (int i = tid; i < 4096; i += 256) {
        int rr = i >> 6, e = i & 63;
        As2[e * 68 + rr] = g_lv[((size_t)(b * 256 + ot * 64 + rr)) * 64 + e];
        Bs2[e * 68 + rr] = g_v [((size_t)(b * 256 + dt * 64 + rr)) * 64 + e];
    }
    __syncthreads();
    int tx = tid & 15, ty = tid >> 4;
    int o0 = ty * 4, d0 = tx * 4;
    float acc[4][4];
    #pragma unroll
    for (int i = 0; i < 4; i++)
        #pragma unroll
        for (int j = 0; j < 4; j++) acc[i][j] = 0.0f;
    #pragma unroll 8
    for (int e = 0; e < 64; e++) {
        float4 a = *(const float4*)&As2[e * 68 + o0];
        float4 qv4 = *(const float4*)&Bs2[e * 68 + d0];
        float av[4] = {a.x, a.y, a.z, a.w};
        float qv[4] = {qv4.x, qv4.y, qv4.z, qv4.w};
        #pragma unroll
        for (int i = 0; i < 4; i++)
            #pragma unroll
            for (int j = 0; j < 4; j++)
                acc[i][j] = fmaf(av[i], qv[j], acc[i][j]);
    }
    #pragma unroll
    for (int i = 0; i < 4; i++) {
        size_t oi = ((size_t)(b * 256 + ot * 64 + o0 + i)) * 256 + dt * 64 + d0;
        *(float4*)&out[oi] = make_float4(acc[i][0], acc[i][1], acc[i][2], acc[i][3]);
    }
}

// ---------------- launch ------------------------------------------------------
extern "C" void kernel_launch(void* const* d_in, const int* in_sizes, int n_in,
                              void* d_out, int out_size)
{
    const float* X     = (const float*)d_in[0];
    const float* dis   = (const float*)d_in[1];
    const float* E     = (const float*)d_in[2];
    const float* Wi    = (const float*)d_in[3];
    const float* Wh    = (const float*)d_in[4];
    const float* bi    = (const float*)d_in[5];
    const float* bh    = (const float*)d_in[6];
    const float* gamma = (const float*)d_in[7];
    const float* beta  = (const float*)d_in[8];
    const float* Wl    = (const float*)d_in[9];
    const float* bl    = (const float*)d_in[10];
    float* out = (float*)d_out;

    cudaFuncSetAttribute(gemm1_mma, cudaFuncAttributeMaxDynamicSharedMemorySize, G2_SMEM);
    cudaFuncSetAttribute(lstm_kernel, cudaFuncAttributeMaxDynamicSharedMemorySize, LSTM_SMEM);

    prep_bias_kernel<<<256, 256>>>(dis, E, Wi, bi, bh);      // idx0
    prep_w_kernel<<<128, 256>>>(Wi, Wh);                     // idx1
    gemm1_mma<<<512, 256, G2_SMEM>>>(X, E, 0);               // idx2
    gemm1_mma<<<512, 256, G2_SMEM>>>(X, E, 65536);           // idx3  <- ncu capture slot
    lstm_kernel<<<128, 256, LSTM_SMEM>>>();                  // idx4
    stats_kernel<<<64, 128>>>();                             // idx5
    vlv_kernel<<<2048, 256>>>(gamma, beta, Wl, bl);          // idx6
    out_kernel<<<512, 256>>>(out);                           // idx7
}